// round 13
// baseline (speedup 1.0000x reference)
#include <cuda_runtime.h>
#include <cuda_bf16.h>
#include <cstdint>

// dynFilter: out[b,1,h,w] = tanh( sum_{c,ky,kx} x[b,c,h+ky-2,w+kx-2] * filt[b, c*25+ky*5+kx, h, w] )
// x [8,4,256,256] f32, filt [8,100,256,256] f32, out [8,1,256,256] f32.
// 210 MB one-pass stream; LDG.128 kernels plateau at DRAM~73% (37.4us) because
// bytes-in-flight/warp is capped at 16B/load. R12 cp.async FIFO failed (issue
// overhead + lockstep waits).
// R13: Blackwell 256-bit loads (ld.global.nc.v8.b32). 8 outputs/thread ->
// 32B/thread/plane, 1024B/warp/load, 5KB in flight per warp per batch (2x).
// 64-thr CTAs, warp = full 256-col row, TILE_H=2, grid 1024 (balanced wave,
// reg cap 128 -> no spill).

#define KK 5
#define PADK 2
#define CC 4
#define HH 256
#define WW 256
#define TILE_H 2
#define NROWS (TILE_H + 2 * PADK)   // 6 halo rows
#define XH 4                        // left halo (aligned window reads need w-4)
#define NCOLS (WW + XH + 4)         // 264 cols: global -4..259
#define NP (CC * KK * KK)           // 100 planes

__device__ __forceinline__ float tanh_approx(float v) {
    float r;
    asm("tanh.approx.f32 %0, %1;" : "=f"(r) : "f"(v));
    return r;
}

// 256-bit non-coherent global load (Blackwell LDG.256).
__device__ __forceinline__ void ldg256(float f[8], const float* p) {
    asm volatile("ld.global.nc.v8.b32 {%0,%1,%2,%3,%4,%5,%6,%7}, [%8];"
                 : "=f"(f[0]), "=f"(f[1]), "=f"(f[2]), "=f"(f[3]),
                   "=f"(f[4]), "=f"(f[5]), "=f"(f[6]), "=f"(f[7])
                 : "l"(p));
}

__global__ __launch_bounds__(64, 8)
void dynfilter_kernel(const float* __restrict__ x,
                      const float* __restrict__ filt,
                      float* __restrict__ out)
{
    const int b   = blockIdx.y;
    const int h0  = blockIdx.x * TILE_H;
    const int tid = threadIdx.x;

    __shared__ __align__(16) float xs[CC][NROWS][NCOLS];   // 25344 B

    // Cooperative halo fill: rows h0-2..h0+3, global cols -4..259 (zero OOB).
    for (int c = 0; c < CC; ++c) {
        #pragma unroll
        for (int r = 0; r < NROWS; ++r) {
            const int gr = h0 - PADK + r;
            const bool rok = (gr >= 0) & (gr < HH);
            const float* xrow = x + (((long)(b * CC + c) * HH + gr) * WW);
            for (int cx = tid; cx < NCOLS; cx += 64) {
                const int gc = cx - XH;
                float v = 0.0f;
                if (rok && gc >= 0 && gc < WW) v = xrow[gc];
                xs[c][r][cx] = v;
            }
        }
    }
    __syncthreads();

    const int hr = tid >> 5;        // 0..1 : warp = one h row
    const int q  = tid & 31;        // lane
    const int h  = h0 + hr;
    const int w  = q << 3;          // 8 outputs per thread, w = 0..248

    float acc[8];
    #pragma unroll
    for (int j = 0; j < 8; ++j) acc[j] = 0.0f;

    // filt plane p, row h, this thread's 8 floats (32B-aligned).
    const long rowstride = (long)WW;                     // floats
    const float* __restrict__ fbase =
        filt + (((long)b * NP) * HH + h) * rowstride + w;
    const long planestep = (long)HH * WW;                // floats per plane

    #pragma unroll
    for (int c = 0; c < CC; ++c) {
        #pragma unroll
        for (int ky = 0; ky < KK; ++ky) {
            // Batch 5 filt LDG.256: 5KB in flight per warp.
            float f[KK][8];
            #pragma unroll
            for (int kx = 0; kx < KK; ++kx) {
                const int p = (c * KK + ky) * KK + kx;
                ldg256(f[kx], fbase + (long)p * planestep);
            }
            // 16-float window (global w-4..w+11) via 4 aligned LDS.128.
            float wv[16];
            #pragma unroll
            for (int t = 0; t < 4; ++t) {
                const float4 v = *(const float4*)&xs[c][hr + ky][w + 4 * t]; // cx = w ↔ global w-4
                wv[4 * t + 0] = v.x; wv[4 * t + 1] = v.y;
                wv[4 * t + 2] = v.z; wv[4 * t + 3] = v.w;
            }
            // out(w+j), tap kx uses x(w+j+kx-2) = wv[j+kx+2]
            #pragma unroll
            for (int kx = 0; kx < KK; ++kx) {
                #pragma unroll
                for (int j = 0; j < 8; ++j)
                    acc[j] = fmaf(wv[j + kx + 2], f[kx][j], acc[j]);
            }
        }
    }

    float4 o0, o1;
    o0.x = tanh_approx(acc[0]); o0.y = tanh_approx(acc[1]);
    o0.z = tanh_approx(acc[2]); o0.w = tanh_approx(acc[3]);
    o1.x = tanh_approx(acc[4]); o1.y = tanh_approx(acc[5]);
    o1.z = tanh_approx(acc[6]); o1.w = tanh_approx(acc[7]);
    float* orow = out + ((long)b * HH + h) * WW + w;
    *(float4*)(orow)     = o0;
    *(float4*)(orow + 4) = o1;
}

extern "C" void kernel_launch(void* const* d_in, const int* in_sizes, int n_in,
                              void* d_out, int out_size)
{
    const float* x    = (const float*)d_in[0];   // [8,4,256,256]
    const float* filt = (const float*)d_in[1];   // [8,100,256,256]
    float* out        = (float*)d_out;           // [8,1,256,256]

    dim3 grid(HH / TILE_H, 8);   // 128 x 8 = 1024 CTAs
    dim3 block(64);
    dynfilter_kernel<<<grid, block>>>(x, filt, out);
}

// round 14
// speedup vs baseline: 1.8540x; 1.8540x over previous
#include <cuda_runtime.h>
#include <cuda_bf16.h>

// dynFilter: out[b,1,h,w] = tanh( sum_{c,ky,kx} x[b,c,h+ky-2,w+kx-2] * filt[b, c*25+ky*5+kx, h, w] )
// x [8,4,256,256] f32, filt [8,100,256,256] f32, out [8,1,256,256] f32.
// 210 MB one-pass stream. Plateau: R4 @ 37.4us, DRAM 73%, 5-load batches.
// R13 lesson: never trade warps for bytes-in-flight at reg cost.
// R14: 10-plane load batches (two ky groups) at UNCHANGED occupancy:
//   f[10] (40 regs) + per-ky 8-float window (8 regs) + accs ~ 60-68 regs,
//   fits launch_bounds(128,7) 72-reg cap. Bytes-in-flight/warp doubles
//   (2.5KB -> 5KB); consumption strictly after the 10-load batch (dataflow-
//   enforced, within one iteration, unlike R7's cross-iteration buffer).

#define KK 5
#define PADK 2
#define CC 4
#define HH 256
#define WW 256
#define TILE_H 4
#define TILE_W 128
#define NROWS (TILE_H + 2 * PADK)        // 8 halo rows
#define NCOLS (TILE_W + 2 * PADK)        // 132 halo cols
#define NCOLS_PAD 136                    // 16B-aligned row stride

__device__ __forceinline__ float tanh_approx(float v) {
    float r;
    asm("tanh.approx.f32 %0, %1;" : "=f"(r) : "f"(v));
    return r;
}

__global__ __launch_bounds__(128, 7)
void dynfilter_kernel(const float* __restrict__ x,
                      const float* __restrict__ filt,
                      float* __restrict__ out)
{
    const int b     = blockIdx.z;
    const int whalf = blockIdx.y;            // 0..1
    const int h0    = blockIdx.x * TILE_H;   // tile row base
    const int w0    = whalf * TILE_W;        // tile col base
    const int tid   = threadIdx.x;

    __shared__ __align__(16) float xs[CC][NROWS][NCOLS_PAD];

    // Cooperative halo load: rows h0-2..h0+5, cols w0-2..w0+129 (zero pad OOB).
    #pragma unroll
    for (int it = 0; it < (CC * NROWS * NCOLS + 127) / 128; ++it) {
        int idx = it * 128 + tid;
        if (idx < CC * NROWS * NCOLS) {
            int c   = idx / (NROWS * NCOLS);
            int rem = idx % (NROWS * NCOLS);
            int r   = rem / NCOLS;
            int col = rem % NCOLS;
            int gr = h0 - PADK + r;
            int gc = w0 - PADK + col;
            float v = 0.0f;
            if (gr >= 0 && gr < HH && gc >= 0 && gc < WW)
                v = x[(((b * CC) + c) * HH + gr) * WW + gc];
            xs[c][r][col] = v;
        }
    }
    __syncthreads();

    const int hr = tid >> 5;       // 0..3 row within tile
    const int q  = tid & 31;       // 0..31 float4 column within tile
    const int h  = h0 + hr;
    const int wl = q << 2;         // local smem col of window start (w-2 incl halo)

    float acc0 = 0.f, acc1 = 0.f, acc2 = 0.f, acc3 = 0.f;

    const long plane = (long)(HH * WW / 4);  // 16384 float4 per plane
    const float4* __restrict__ fp =
        (const float4*)filt +
        (((long)b * (CC * KK * KK) * HH + h) * (WW / 4) + (whalf * 32 + q));

    // Consume one ky group's 5 loaded planes against its 8-float window row.
    #define CONSUME(c_, ky_, F)                                                 \
        do {                                                                    \
            const float4 a_  = *(const float4*)&xs[c_][hr + (ky_)][wl];         \
            const float4 b_  = *(const float4*)&xs[c_][hr + (ky_)][wl + 4];     \
            const float x0_ = a_.x, x1_ = a_.y, x2_ = a_.z, x3_ = a_.w;         \
            const float x4_ = b_.x, x5_ = b_.y, x6_ = b_.z, x7_ = b_.w;         \
            acc0 = fmaf(x0_, F[0].x, acc0); acc1 = fmaf(x1_, F[0].y, acc1);     \
            acc2 = fmaf(x2_, F[0].z, acc2); acc3 = fmaf(x3_, F[0].w, acc3);     \
            acc0 = fmaf(x1_, F[1].x, acc0); acc1 = fmaf(x2_, F[1].y, acc1);     \
            acc2 = fmaf(x3_, F[1].z, acc2); acc3 = fmaf(x4_, F[1].w, acc3);     \
            acc0 = fmaf(x2_, F[2].x, acc0); acc1 = fmaf(x3_, F[2].y, acc1);     \
            acc2 = fmaf(x4_, F[2].z, acc2); acc3 = fmaf(x5_, F[2].w, acc3);     \
            acc0 = fmaf(x3_, F[3].x, acc0); acc1 = fmaf(x4_, F[3].y, acc1);     \
            acc2 = fmaf(x5_, F[3].z, acc2); acc3 = fmaf(x6_, F[3].w, acc3);     \
            acc0 = fmaf(x4_, F[4].x, acc0); acc1 = fmaf(x5_, F[4].y, acc1);     \
            acc2 = fmaf(x6_, F[4].z, acc2); acc3 = fmaf(x7_, F[4].w, acc3);     \
        } while (0)

    #pragma unroll
    for (int c = 0; c < CC; ++c) {
        const long cb = (long)c * (KK * KK) * plane;

        // ---- Batch 1: ky=0,1  (10 LDG.128 issued before any consumption) ----
        {
            float4 fa[KK], fb[KK];
            #pragma unroll
            for (int kx = 0; kx < KK; ++kx) fa[kx] = __ldcs(fp + cb + (long)(0 * KK + kx) * plane);
            #pragma unroll
            for (int kx = 0; kx < KK; ++kx) fb[kx] = __ldcs(fp + cb + (long)(1 * KK + kx) * plane);
            CONSUME(c, 0, fa);
            CONSUME(c, 1, fb);
        }
        // ---- Batch 2: ky=2,3 ----
        {
            float4 fa[KK], fb[KK];
            #pragma unroll
            for (int kx = 0; kx < KK; ++kx) fa[kx] = __ldcs(fp + cb + (long)(2 * KK + kx) * plane);
            #pragma unroll
            for (int kx = 0; kx < KK; ++kx) fb[kx] = __ldcs(fp + cb + (long)(3 * KK + kx) * plane);
            CONSUME(c, 2, fa);
            CONSUME(c, 3, fb);
        }
        // ---- Batch 3: ky=4 (5 planes) ----
        {
            float4 fa[KK];
            #pragma unroll
            for (int kx = 0; kx < KK; ++kx) fa[kx] = __ldcs(fp + cb + (long)(4 * KK + kx) * plane);
            CONSUME(c, 4, fa);
        }
    }
    #undef CONSUME

    float4 o;
    o.x = tanh_approx(acc0);
    o.y = tanh_approx(acc1);
    o.z = tanh_approx(acc2);
    o.w = tanh_approx(acc3);
    ((float4*)out)[((long)b * HH + h) * (WW / 4) + whalf * 32 + q] = o;
}

extern "C" void kernel_launch(void* const* d_in, const int* in_sizes, int n_in,
                              void* d_out, int out_size)
{
    const float* x    = (const float*)d_in[0];   // [8,4,256,256]
    const float* filt = (const float*)d_in[1];   // [8,100,256,256]
    float* out        = (float*)d_out;           // [8,1,256,256]

    dim3 grid(HH / TILE_H, WW / TILE_W, 8);   // 64 x 2 x 8 = 1024 CTAs
    dim3 block(128);
    dynfilter_kernel<<<grid, block>>>(x, filt, out);
}